// round 13
// baseline (speedup 1.0000x reference)
#include <cuda_runtime.h>
#include <cuda_bf16.h>
#include <math.h>

#define BATCH 4096
#define P 256
#define FCH 20
#define HH 18
#define WW 18
#define HWSZ (HH*WW)          // 324
#define VOL (FCH*HWSZ)        // 6480
#define TB 16                 // batches per CTA in params kernel
#define PI_CONST 3.14159f
#define PW 20                 // padded plane width (x in [-1,18] -> idx 0..19)
#define PAREA (PW*PW)         // 400

// Scratch: per (b,f): {A, B, X, Y} fully-fused affine (float4-aligned)
__device__ __align__(16) float g_par[(size_t)BATCH * FCH * 4];

// ---- packed fp32x2 helpers (Blackwell FFMA2, PTX-only) ---------------------
__device__ __forceinline__ void ffma2(unsigned long long& d,
                                      unsigned long long a,
                                      unsigned long long b) {
    asm("fma.rn.f32x2 %0, %1, %2, %0;" : "+l"(d) : "l"(a), "l"(b));
}
__device__ __forceinline__ unsigned long long splat2(float w) {
    unsigned long long r;
    asm("mov.b64 %0, {%1, %1};" : "=l"(r) : "f"(w));
    return r;
}
__device__ __forceinline__ float2 unpack2(unsigned long long v) {
    float2 r;
    asm("mov.b64 {%0, %1}, %2;" : "=f"(r.x), "=f"(r.y) : "l"(v));
    return r;
}

// ---- fast transcendentals (MUFU-based, ~1e-6 accuracy, no slow paths) ------
__device__ __forceinline__ float fast_tanh(float x) {
    return 1.f - __fdividef(2.f, __expf(2.f * x) + 1.f);
}
__device__ __forceinline__ float fast_sigmoid(float x) {
    return __fdividef(1.f, 1.f + __expf(-x));
}

// ---------------------------------------------------------------------------
// Kernel 1 (R11 version): MLP head -> fused params
// grid: BATCH/TB = 256 blocks, 256 threads
// ---------------------------------------------------------------------------
__global__ __launch_bounds__(256) void params_kernel(
    const float* __restrict__ pc,   // (B,P)
    const float* __restrict__ W1,   // (P,P)
    const float* __restrict__ b1,   // (P,)
    const float* __restrict__ Ws,   // (P,20)
    const float* __restrict__ bs,   // (20,)
    const float* __restrict__ Wr,   // (P,20)
    const float* __restrict__ br,   // (20,)
    const float* __restrict__ Wt,   // (P,40)
    const float* __restrict__ bt)   // (40,)
{
    __shared__ __align__(16) float pc_s[P][TB];   // transposed: [i][b]
    __shared__ __align__(16) float h_t[P][TB];    // h transposed: [i][b]
    __shared__ float red[3][80][TB];              // head partials

    const int tid = threadIdx.x;
    const int b0 = blockIdx.x * TB;

    #pragma unroll
    for (int b = 0; b < TB; b++)
        pc_s[tid][b] = pc[(size_t)(b0 + b) * P + tid];
    __syncthreads();

    unsigned long long accp[TB / 2];
    #pragma unroll
    for (int k = 0; k < TB / 2; k++) accp[k] = 0ull;

    const int U = 8;
    float cur[U], nxt[U];
    #pragma unroll
    for (int j = 0; j < U; j++) cur[j] = W1[j * P + tid];

    for (int i0 = 0; i0 < P; i0 += U) {
        const int inext = i0 + U;
        if (inext < P) {
            #pragma unroll
            for (int j = 0; j < U; j++) nxt[j] = W1[(inext + j) * P + tid];
        }
        #pragma unroll
        for (int j = 0; j < U; j++) {
            const unsigned long long wpj = splat2(cur[j]);
            const ulonglong2* pr = (const ulonglong2*)pc_s[i0 + j];
            const ulonglong2 q0 = pr[0], q1 = pr[1], q2 = pr[2], q3 = pr[3];
            ffma2(accp[0], q0.x, wpj);  ffma2(accp[1], q0.y, wpj);
            ffma2(accp[2], q1.x, wpj);  ffma2(accp[3], q1.y, wpj);
            ffma2(accp[4], q2.x, wpj);  ffma2(accp[5], q2.y, wpj);
            ffma2(accp[6], q3.x, wpj);  ffma2(accp[7], q3.y, wpj);
        }
        #pragma unroll
        for (int j = 0; j < U; j++) cur[j] = nxt[j];
    }

    const float bias1 = b1[tid];
    #pragma unroll
    for (int k = 0; k < TB / 2; k++) {
        const float2 f = unpack2(accp[k]);
        h_t[tid][2 * k + 0] = fmaxf(f.x + bias1, 0.f);
        h_t[tid][2 * k + 1] = fmaxf(f.y + bias1, 0.f);
    }
    __syncthreads();

    if (tid < 240) {
        const int col = tid % 80;
        const int seg = tid / 80;

        const float* wp;
        int ld;
        if (col < 20)      { wp = Ws + col;        ld = 20; }
        else if (col < 40) { wp = Wr + (col - 20); ld = 20; }
        else               { wp = Wt + (col - 40); ld = 40; }

        unsigned long long hacc[TB / 2];
        #pragma unroll
        for (int k = 0; k < TB / 2; k++) hacc[k] = 0ull;

        const float* wptr = wp + seg * ld;
        const int step = 3 * ld;
        for (int i = seg; i < P; i += 3) {
            const unsigned long long wpj = splat2(*wptr);
            wptr += step;
            const ulonglong2* hr = (const ulonglong2*)h_t[i];
            const ulonglong2 q0 = hr[0], q1 = hr[1], q2 = hr[2], q3 = hr[3];
            ffma2(hacc[0], q0.x, wpj);  ffma2(hacc[1], q0.y, wpj);
            ffma2(hacc[2], q1.x, wpj);  ffma2(hacc[3], q1.y, wpj);
            ffma2(hacc[4], q2.x, wpj);  ffma2(hacc[5], q2.y, wpj);
            ffma2(hacc[6], q3.x, wpj);  ffma2(hacc[7], q3.y, wpj);
        }
        #pragma unroll
        for (int k = 0; k < TB / 2; k++) {
            const float2 f = unpack2(hacc[k]);
            red[seg][col][2 * k + 0] = f.x;
            red[seg][col][2 * k + 1] = f.y;
        }
    }
    __syncthreads();

    for (int o = tid; o < TB * FCH; o += 256) {
        const int b = o / FCH;
        const int f = o - b * FCH;

        const float vs = red[0][f][b] + red[1][f][b] + red[2][f][b] + bs[f];
        const float vr = red[0][20 + f][b] + red[1][20 + f][b] + red[2][20 + f][b] + br[f];
        const float vt0 = red[0][40 + 2*f][b] + red[1][40 + 2*f][b] + red[2][40 + 2*f][b] + bt[2*f];
        const float vt1 = red[0][41 + 2*f][b] + red[1][41 + 2*f][b] + red[2][41 + 2*f][b] + bt[2*f + 1];

        const float scale = 2.f * fast_sigmoid(vs);
        const float ang = fast_tanh(vr) * PI_CONST;
        const float s = __sinf(ang);
        const float c = __cosf(ang);
        const float s9 = scale * 9.f;

        float4 out4;
        out4.x = c * s9;                               // A
        out4.y = s * s9;                               // B
        out4.z = (fast_tanh(vt0) + 1.f) * 9.f - 0.5f;  // X
        out4.w = (fast_tanh(vt1) + 1.f) * 9.f - 0.5f;  // Y
        ((float4*)g_par)[(size_t)(b0 + b) * FCH + f] = out4;
    }
}

// ---------------------------------------------------------------------------
// Kernel 2 (exact R6/R9 version, measured 52.5us)
// ---------------------------------------------------------------------------
__global__ __launch_bounds__(352) void sample_kernel(
    const float* __restrict__ fm,   // (B,20,18,18)
    float* __restrict__ out)        // (B,20,18,18)
{
    __shared__ __align__(16) float bl[FCH][PAREA];  // 32 KB padded planes
    __shared__ __align__(16) float4 par_s[FCH];     // {A,B,X,Y} per channel

    const int b = blockIdx.x;
    const int tid = threadIdx.x;

    if (tid < FCH)
        par_s[tid] = ((const float4*)g_par)[(size_t)b * FCH + tid];

    for (int i = tid; i < FCH * 76; i += 352) {
        const int f = i / 76;
        const int k = i - f * 76;
        int idx;
        if (k < 20)      idx = k;                  // row 0
        else if (k < 40) idx = 380 + (k - 20);     // row 19
        else if (k < 58) idx = (k - 39) * PW;      // col 0, rows 1..18
        else             idx = (k - 57) * PW + 19; // col 19, rows 1..18
        bl[f][idx] = 0.f;
    }

    const float* base = fm + (size_t)b * VOL;
    const int py = tid / WW;
    const int px = tid - py * WW;

    if (tid < HWSZ) {
        const int pidx = (py + 1) * PW + (px + 1);
        #pragma unroll
        for (int f = 0; f < FCH; f++) {
            const float iz = f * (20.f / 19.f) - 0.5f;
            const float z0f = floorf(iz);
            const float wz = iz - z0f;
            const int z0 = (int)z0f;
            const float v0 = (z0 >= 0)      ? base[z0 * HWSZ + tid]       : 0.f;
            const float v1 = (z0 + 1 < FCH) ? base[(z0 + 1) * HWSZ + tid] : 0.f;
            bl[f][pidx] = (1.f - wz) * v0 + wz * v1;
        }
    }
    __syncthreads();

    if (tid < HWSZ) {
        const float gx = px * (2.f / 17.f) - 1.f;
        const float gy = py * (2.f / 17.f) - 1.f;
        float* ob = out + (size_t)b * VOL + tid;

        #pragma unroll 4
        for (int f = 0; f < FCH; f++) {
            const float4 p = par_s[f];

            float ix = fmaf(p.x, gx, fmaf(-p.y, gy, p.z));  // A*gx - B*gy + X
            float iy = fmaf(p.y, gx, fmaf(p.x, gy, p.w));   // B*gx + A*gy + Y

            ix = fminf(fmaxf(ix, -1.f), 17.999998f);
            iy = fminf(fmaxf(iy, -1.f), 17.999998f);

            const float x0f = floorf(ix), y0f = floorf(iy);
            const float wx = ix - x0f, wy = iy - y0f;
            const int xi = (int)x0f + 1;   // [0,18]
            const int yi = (int)y0f + 1;   // [0,18]

            const float* q = &bl[f][yi * PW + xi];
            const float t00 = q[0],  t01 = q[1];
            const float t10 = q[PW], t11 = q[PW + 1];
            const float r0 = fmaf(wx, t01 - t00, t00);
            const float r1 = fmaf(wx, t11 - t10, t10);
            ob[f * HWSZ] = fmaf(wy, r1 - r0, r0);
        }
    }
}

// ---------------------------------------------------------------------------
// DIAGNOSTIC ROUND: a third (redundant, identical) params launch is appended
// so ncu's fixed capture slot (-s 5 -c 1 => global launch idx 5) lands on
// params_kernel for the first time. Deterministic: it rewrites g_par with
// the same values after sample_kernel has consumed them; output unchanged.
// ---------------------------------------------------------------------------
extern "C" void kernel_launch(void* const* d_in, const int* in_sizes, int n_in,
                              void* d_out, int out_size)
{
    const float* feature_map = (const float*)d_in[0];
    const float* para_code   = (const float*)d_in[1];
    const float* W1 = (const float*)d_in[2];
    const float* b1 = (const float*)d_in[3];
    const float* Ws = (const float*)d_in[4];
    const float* bs = (const float*)d_in[5];
    const float* Wr = (const float*)d_in[6];
    const float* br = (const float*)d_in[7];
    const float* Wt = (const float*)d_in[8];
    const float* bt = (const float*)d_in[9];
    float* out = (float*)d_out;

    params_kernel<<<BATCH / TB, 256>>>(para_code, W1, b1, Ws, bs, Wr, br, Wt, bt);
    sample_kernel<<<BATCH, 352>>>(feature_map, out);
    // diagnostic replica (see comment above)
    params_kernel<<<BATCH / TB, 256>>>(para_code, W1, b1, Ws, bs, Wr, br, Wt, bt);
}

// round 14
// speedup vs baseline: 1.3042x; 1.3042x over previous
#include <cuda_runtime.h>
#include <cuda_bf16.h>
#include <math.h>

#define BATCH 4096
#define P 256
#define FCH 20
#define HH 18
#define WW 18
#define HWSZ (HH*WW)          // 324
#define VOL (FCH*HWSZ)        // 6480
#define TB 16                 // batches per CTA in params kernel
#define NSEG 6                // head segments
#define PI_CONST 3.14159f
#define PW 20                 // padded plane width (x in [-1,18] -> idx 0..19)
#define PAREA (PW*PW)         // 400

// Scratch: per (b,f): {A, B, X, Y} fully-fused affine (float4-aligned)
__device__ __align__(16) float g_par[(size_t)BATCH * FCH * 4];

// ---- packed fp32x2 helpers (Blackwell FFMA2, PTX-only) ---------------------
__device__ __forceinline__ void ffma2(unsigned long long& d,
                                      unsigned long long a,
                                      unsigned long long b) {
    asm("fma.rn.f32x2 %0, %1, %2, %0;" : "+l"(d) : "l"(a), "l"(b));
}
__device__ __forceinline__ unsigned long long splat2(float w) {
    unsigned long long r;
    asm("mov.b64 %0, {%1, %1};" : "=l"(r) : "f"(w));
    return r;
}
__device__ __forceinline__ float2 unpack2(unsigned long long v) {
    float2 r;
    asm("mov.b64 {%0, %1}, %2;" : "=f"(r.x), "=f"(r.y) : "l"(v));
    return r;
}

// ---- fast transcendentals (MUFU-based, ~1e-6 accuracy) ---------------------
__device__ __forceinline__ float fast_tanh(float x) {
    return 1.f - __fdividef(2.f, __expf(2.f * x) + 1.f);
}
__device__ __forceinline__ float fast_sigmoid(float x) {
    return __fdividef(1.f, 1.f + __expf(-x));
}

// ---------------------------------------------------------------------------
// Kernel 1: MLP head -> fused params. 512 threads (16 warps) per CTA,
// K-split GEMV (thread = (col, half)) to double warps/SM at grid=256.
// ---------------------------------------------------------------------------
__global__ __launch_bounds__(512, 2) void params_kernel(
    const float* __restrict__ pc,   // (B,P)
    const float* __restrict__ W1,   // (P,P)
    const float* __restrict__ b1,   // (P,)
    const float* __restrict__ Ws,   // (P,20)
    const float* __restrict__ bs,   // (20,)
    const float* __restrict__ Wr,   // (P,20)
    const float* __restrict__ br,   // (20,)
    const float* __restrict__ Wt,   // (P,40)
    const float* __restrict__ bt)   // (40,)
{
    __shared__ __align__(16) float pc_s[P][TB];       // 16 KB, [i][b]
    __shared__ __align__(16) float h_t[P][TB];        // 16 KB, [i][b]
    __shared__ __align__(16) float part[P][TB + 1];   // 17 KB, K-split partials
    __shared__ float red[NSEG][80][TB];               // 30.7 KB head partials

    const int tid = threadIdx.x;
    const int b0 = blockIdx.x * TB;

    // Load pc transposed: idx = b*256 + i, consecutive tid -> consecutive i
    #pragma unroll
    for (int idx = tid; idx < P * TB; idx += 512) {
        const int b = idx >> 8;
        const int i = idx & 255;
        pc_s[i][b] = pc[(size_t)(b0 + b) * P + i];
    }
    __syncthreads();

    // ---- GEMV (K-split): half covers i in [half*128, half*128+128) ----
    const int col = tid & 255;
    const int half = tid >> 8;
    const int ibase = half * 128;

    unsigned long long accp[TB / 2];
    #pragma unroll
    for (int k = 0; k < TB / 2; k++) accp[k] = 0ull;

    const int U = 8;
    float cur[U], nxt[U];
    #pragma unroll
    for (int j = 0; j < U; j++) cur[j] = W1[(ibase + j) * P + col];

    for (int t0 = 0; t0 < 128; t0 += U) {
        const int tnext = t0 + U;
        if (tnext < 128) {
            #pragma unroll
            for (int j = 0; j < U; j++) nxt[j] = W1[(ibase + tnext + j) * P + col];
        }
        #pragma unroll
        for (int j = 0; j < U; j++) {
            const unsigned long long wpj = splat2(cur[j]);
            const ulonglong2* pr = (const ulonglong2*)pc_s[ibase + t0 + j];
            const ulonglong2 q0 = pr[0], q1 = pr[1], q2 = pr[2], q3 = pr[3];
            ffma2(accp[0], q0.x, wpj);  ffma2(accp[1], q0.y, wpj);
            ffma2(accp[2], q1.x, wpj);  ffma2(accp[3], q1.y, wpj);
            ffma2(accp[4], q2.x, wpj);  ffma2(accp[5], q2.y, wpj);
            ffma2(accp[6], q3.x, wpj);  ffma2(accp[7], q3.y, wpj);
        }
        #pragma unroll
        for (int j = 0; j < U; j++) cur[j] = nxt[j];
    }

    // K-split reduce: half 1 dumps partials, half 0 combines (+bias, relu)
    if (half == 1) {
        #pragma unroll
        for (int k = 0; k < TB / 2; k++) {
            const float2 f = unpack2(accp[k]);
            part[col][2 * k + 0] = f.x;
            part[col][2 * k + 1] = f.y;
        }
    }
    __syncthreads();
    if (half == 0) {
        const float bias1 = b1[col];
        #pragma unroll
        for (int k = 0; k < TB / 2; k++) {
            const float2 f = unpack2(accp[k]);
            h_t[col][2 * k + 0] = fmaxf(f.x + part[col][2 * k + 0] + bias1, 0.f);
            h_t[col][2 * k + 1] = fmaxf(f.y + part[col][2 * k + 1] + bias1, 0.f);
        }
    }
    __syncthreads();

    // ---- Heads: 80 cols x 6 interleaved segments (480 active threads) ----
    if (tid < 80 * NSEG) {
        const int hcol = tid % 80;
        const int seg = tid / 80;

        const float* wp;
        int ld;
        if (hcol < 20)      { wp = Ws + hcol;        ld = 20; }
        else if (hcol < 40) { wp = Wr + (hcol - 20); ld = 20; }
        else                { wp = Wt + (hcol - 40); ld = 40; }

        unsigned long long hacc[TB / 2];
        #pragma unroll
        for (int k = 0; k < TB / 2; k++) hacc[k] = 0ull;

        const float* wptr = wp + seg * ld;
        const int step = NSEG * ld;
        for (int i = seg; i < P; i += NSEG) {
            const unsigned long long wpj = splat2(*wptr);
            wptr += step;
            const ulonglong2* hr = (const ulonglong2*)h_t[i];
            const ulonglong2 q0 = hr[0], q1 = hr[1], q2 = hr[2], q3 = hr[3];
            ffma2(hacc[0], q0.x, wpj);  ffma2(hacc[1], q0.y, wpj);
            ffma2(hacc[2], q1.x, wpj);  ffma2(hacc[3], q1.y, wpj);
            ffma2(hacc[4], q2.x, wpj);  ffma2(hacc[5], q2.y, wpj);
            ffma2(hacc[6], q3.x, wpj);  ffma2(hacc[7], q3.y, wpj);
        }
        #pragma unroll
        for (int k = 0; k < TB / 2; k++) {
            const float2 f = unpack2(hacc[k]);
            red[seg][hcol][2 * k + 0] = f.x;
            red[seg][hcol][2 * k + 1] = f.y;
        }
    }
    __syncthreads();

    // ---- Epilogue: one thread per (b,f) ----
    if (tid < TB * FCH) {
        const int b = tid / FCH;
        const int f = tid - b * FCH;

        float vs = bs[f], vr = br[f], vt0 = bt[2 * f], vt1 = bt[2 * f + 1];
        #pragma unroll
        for (int s6 = 0; s6 < NSEG; s6++) {
            vs  += red[s6][f][b];
            vr  += red[s6][20 + f][b];
            vt0 += red[s6][40 + 2 * f][b];
            vt1 += red[s6][41 + 2 * f][b];
        }

        const float scale = 2.f * fast_sigmoid(vs);
        const float ang = fast_tanh(vr) * PI_CONST;
        const float s = __sinf(ang);
        const float c = __cosf(ang);
        const float s9 = scale * 9.f;

        float4 out4;
        out4.x = c * s9;                               // A
        out4.y = s * s9;                               // B
        out4.z = (fast_tanh(vt0) + 1.f) * 9.f - 0.5f;  // X
        out4.w = (fast_tanh(vt1) + 1.f) * 9.f - 0.5f;  // Y
        ((float4*)g_par)[(size_t)(b0 + b) * FCH + f] = out4;
    }
}

// ---------------------------------------------------------------------------
// Kernel 2 (exact R6/R9 version, measured 52.5us): z-preblended sample over
// zero-bordered 20x20 planes. grid: BATCH blocks, 352 threads
// ---------------------------------------------------------------------------
__global__ __launch_bounds__(352) void sample_kernel(
    const float* __restrict__ fm,   // (B,20,18,18)
    float* __restrict__ out)        // (B,20,18,18)
{
    __shared__ __align__(16) float bl[FCH][PAREA];  // 32 KB padded planes
    __shared__ __align__(16) float4 par_s[FCH];     // {A,B,X,Y} per channel

    const int b = blockIdx.x;
    const int tid = threadIdx.x;

    if (tid < FCH)
        par_s[tid] = ((const float4*)g_par)[(size_t)b * FCH + tid];

    for (int i = tid; i < FCH * 76; i += 352) {
        const int f = i / 76;
        const int k = i - f * 76;
        int idx;
        if (k < 20)      idx = k;                  // row 0
        else if (k < 40) idx = 380 + (k - 20);     // row 19
        else if (k < 58) idx = (k - 39) * PW;      // col 0, rows 1..18
        else             idx = (k - 57) * PW + 19; // col 19, rows 1..18
        bl[f][idx] = 0.f;
    }

    const float* base = fm + (size_t)b * VOL;
    const int py = tid / WW;
    const int px = tid - py * WW;

    if (tid < HWSZ) {
        const int pidx = (py + 1) * PW + (px + 1);
        #pragma unroll
        for (int f = 0; f < FCH; f++) {
            const float iz = f * (20.f / 19.f) - 0.5f;
            const float z0f = floorf(iz);
            const float wz = iz - z0f;
            const int z0 = (int)z0f;
            const float v0 = (z0 >= 0)      ? base[z0 * HWSZ + tid]       : 0.f;
            const float v1 = (z0 + 1 < FCH) ? base[(z0 + 1) * HWSZ + tid] : 0.f;
            bl[f][pidx] = (1.f - wz) * v0 + wz * v1;
        }
    }
    __syncthreads();

    if (tid < HWSZ) {
        const float gx = px * (2.f / 17.f) - 1.f;
        const float gy = py * (2.f / 17.f) - 1.f;
        float* ob = out + (size_t)b * VOL + tid;

        #pragma unroll 4
        for (int f = 0; f < FCH; f++) {
            const float4 p = par_s[f];

            float ix = fmaf(p.x, gx, fmaf(-p.y, gy, p.z));  // A*gx - B*gy + X
            float iy = fmaf(p.y, gx, fmaf(p.x, gy, p.w));   // B*gx + A*gy + Y

            ix = fminf(fmaxf(ix, -1.f), 17.999998f);
            iy = fminf(fmaxf(iy, -1.f), 17.999998f);

            const float x0f = floorf(ix), y0f = floorf(iy);
            const float wx = ix - x0f, wy = iy - y0f;
            const int xi = (int)x0f + 1;   // [0,18]
            const int yi = (int)y0f + 1;   // [0,18]

            const float* q = &bl[f][yi * PW + xi];
            const float t00 = q[0],  t01 = q[1];
            const float t10 = q[PW], t11 = q[PW + 1];
            const float r0 = fmaf(wx, t01 - t00, t00);
            const float r1 = fmaf(wx, t11 - t10, t10);
            ob[f * HWSZ] = fmaf(wy, r1 - r0, r0);
        }
    }
}

// ---------------------------------------------------------------------------
extern "C" void kernel_launch(void* const* d_in, const int* in_sizes, int n_in,
                              void* d_out, int out_size)
{
    const float* feature_map = (const float*)d_in[0];
    const float* para_code   = (const float*)d_in[1];
    const float* W1 = (const float*)d_in[2];
    const float* b1 = (const float*)d_in[3];
    const float* Ws = (const float*)d_in[4];
    const float* bs = (const float*)d_in[5];
    const float* Wr = (const float*)d_in[6];
    const float* br = (const float*)d_in[7];
    const float* Wt = (const float*)d_in[8];
    const float* bt = (const float*)d_in[9];
    float* out = (float*)d_out;

    params_kernel<<<BATCH / TB, 512>>>(para_code, W1, b1, Ws, bs, Wr, br, Wt, bt);
    sample_kernel<<<BATCH, 352>>>(feature_map, out);
}

// round 15
// speedup vs baseline: 1.3606x; 1.0432x over previous
#include <cuda_runtime.h>
#include <cuda_bf16.h>
#include <math.h>

#define BATCH 4096
#define P 256
#define FCH 20
#define HH 18
#define WW 18
#define HWSZ (HH*WW)          // 324
#define VOL (FCH*HWSZ)        // 6480
#define TB 16                 // batches per CTA in params kernel
#define PI_CONST 3.14159f
#define PW 20                 // padded plane width (x in [-1,18] -> idx 0..19)
#define PAREA (PW*PW)         // 400

// Scratch: per (b,f): {A, B, X, Y} fully-fused affine (float4-aligned)
__device__ __align__(16) float g_par[(size_t)BATCH * FCH * 4];

// ---- packed fp32x2 helpers (Blackwell FFMA2, PTX-only) ---------------------
__device__ __forceinline__ void ffma2(unsigned long long& d,
                                      unsigned long long a,
                                      unsigned long long b) {
    asm("fma.rn.f32x2 %0, %1, %2, %0;" : "+l"(d) : "l"(a), "l"(b));
}
__device__ __forceinline__ unsigned long long splat2(float w) {
    unsigned long long r;
    asm("mov.b64 %0, {%1, %1};" : "=l"(r) : "f"(w));
    return r;
}
__device__ __forceinline__ float2 unpack2(unsigned long long v) {
    float2 r;
    asm("mov.b64 {%0, %1}, %2;" : "=f"(r.x), "=f"(r.y) : "l"(v));
    return r;
}

// ---- fast transcendentals (MUFU-based, ~1e-6 accuracy) ---------------------
__device__ __forceinline__ float fast_tanh(float x) {
    return 1.f - __fdividef(2.f, __expf(2.f * x) + 1.f);
}
__device__ __forceinline__ float fast_sigmoid(float x) {
    return __fdividef(1.f, 1.f + __expf(-x));
}

// ---------------------------------------------------------------------------
// Kernel 1 (R11/R13 version, measured 33.7us): MLP head -> fused params
// grid: BATCH/TB = 256 blocks, 256 threads
// ---------------------------------------------------------------------------
__global__ __launch_bounds__(256) void params_kernel(
    const float* __restrict__ pc,   // (B,P)
    const float* __restrict__ W1,   // (P,P)
    const float* __restrict__ b1,   // (P,)
    const float* __restrict__ Ws,   // (P,20)
    const float* __restrict__ bs,   // (20,)
    const float* __restrict__ Wr,   // (P,20)
    const float* __restrict__ br,   // (20,)
    const float* __restrict__ Wt,   // (P,40)
    const float* __restrict__ bt)   // (40,)
{
    __shared__ __align__(16) float pc_s[P][TB];   // transposed: [i][b]
    __shared__ __align__(16) float h_t[P][TB];    // h transposed: [i][b]
    __shared__ float red[3][80][TB];              // head partials

    const int tid = threadIdx.x;
    const int b0 = blockIdx.x * TB;

    #pragma unroll
    for (int b = 0; b < TB; b++)
        pc_s[tid][b] = pc[(size_t)(b0 + b) * P + tid];
    __syncthreads();

    unsigned long long accp[TB / 2];
    #pragma unroll
    for (int k = 0; k < TB / 2; k++) accp[k] = 0ull;

    const int U = 8;
    float cur[U], nxt[U];
    #pragma unroll
    for (int j = 0; j < U; j++) cur[j] = W1[j * P + tid];

    for (int i0 = 0; i0 < P; i0 += U) {
        const int inext = i0 + U;
        if (inext < P) {
            #pragma unroll
            for (int j = 0; j < U; j++) nxt[j] = W1[(inext + j) * P + tid];
        }
        #pragma unroll
        for (int j = 0; j < U; j++) {
            const unsigned long long wpj = splat2(cur[j]);
            const ulonglong2* pr = (const ulonglong2*)pc_s[i0 + j];
            const ulonglong2 q0 = pr[0], q1 = pr[1], q2 = pr[2], q3 = pr[3];
            ffma2(accp[0], q0.x, wpj);  ffma2(accp[1], q0.y, wpj);
            ffma2(accp[2], q1.x, wpj);  ffma2(accp[3], q1.y, wpj);
            ffma2(accp[4], q2.x, wpj);  ffma2(accp[5], q2.y, wpj);
            ffma2(accp[6], q3.x, wpj);  ffma2(accp[7], q3.y, wpj);
        }
        #pragma unroll
        for (int j = 0; j < U; j++) cur[j] = nxt[j];
    }

    const float bias1 = b1[tid];
    #pragma unroll
    for (int k = 0; k < TB / 2; k++) {
        const float2 f = unpack2(accp[k]);
        h_t[tid][2 * k + 0] = fmaxf(f.x + bias1, 0.f);
        h_t[tid][2 * k + 1] = fmaxf(f.y + bias1, 0.f);
    }
    __syncthreads();

    if (tid < 240) {
        const int col = tid % 80;
        const int seg = tid / 80;

        const float* wp;
        int ld;
        if (col < 20)      { wp = Ws + col;        ld = 20; }
        else if (col < 40) { wp = Wr + (col - 20); ld = 20; }
        else               { wp = Wt + (col - 40); ld = 40; }

        unsigned long long hacc[TB / 2];
        #pragma unroll
        for (int k = 0; k < TB / 2; k++) hacc[k] = 0ull;

        const float* wptr = wp + seg * ld;
        const int step = 3 * ld;
        for (int i = seg; i < P; i += 3) {
            const unsigned long long wpj = splat2(*wptr);
            wptr += step;
            const ulonglong2* hr = (const ulonglong2*)h_t[i];
            const ulonglong2 q0 = hr[0], q1 = hr[1], q2 = hr[2], q3 = hr[3];
            ffma2(hacc[0], q0.x, wpj);  ffma2(hacc[1], q0.y, wpj);
            ffma2(hacc[2], q1.x, wpj);  ffma2(hacc[3], q1.y, wpj);
            ffma2(hacc[4], q2.x, wpj);  ffma2(hacc[5], q2.y, wpj);
            ffma2(hacc[6], q3.x, wpj);  ffma2(hacc[7], q3.y, wpj);
        }
        #pragma unroll
        for (int k = 0; k < TB / 2; k++) {
            const float2 f = unpack2(hacc[k]);
            red[seg][col][2 * k + 0] = f.x;
            red[seg][col][2 * k + 1] = f.y;
        }
    }
    __syncthreads();

    for (int o = tid; o < TB * FCH; o += 256) {
        const int b = o / FCH;
        const int f = o - b * FCH;

        const float vs = red[0][f][b] + red[1][f][b] + red[2][f][b] + bs[f];
        const float vr = red[0][20 + f][b] + red[1][20 + f][b] + red[2][20 + f][b] + br[f];
        const float vt0 = red[0][40 + 2*f][b] + red[1][40 + 2*f][b] + red[2][40 + 2*f][b] + bt[2*f];
        const float vt1 = red[0][41 + 2*f][b] + red[1][41 + 2*f][b] + red[2][41 + 2*f][b] + bt[2*f + 1];

        const float scale = 2.f * fast_sigmoid(vs);
        const float ang = fast_tanh(vr) * PI_CONST;
        const float s = __sinf(ang);
        const float c = __cosf(ang);
        const float s9 = scale * 9.f;

        float4 out4;
        out4.x = c * s9;                               // A
        out4.y = s * s9;                               // B
        out4.z = (fast_tanh(vt0) + 1.f) * 9.f - 0.5f;  // X
        out4.w = (fast_tanh(vt1) + 1.f) * 9.f - 0.5f;  // Y
        ((float4*)g_par)[(size_t)(b0 + b) * FCH + f] = out4;
    }
}

// ---------------------------------------------------------------------------
// Kernel 2: R11 structure with block 324 (all threads active) and 6 CTAs/SM
// for higher occupancy. grid: BATCH blocks, 324 threads.
// ---------------------------------------------------------------------------
__global__ __launch_bounds__(324, 6) void sample_kernel(
    const float* __restrict__ fm,   // (B,20,18,18)
    float* __restrict__ out)        // (B,20,18,18)
{
    __shared__ __align__(16) float bl[FCH][PAREA];  // 32 KB padded planes
    __shared__ __align__(16) float4 par_s[FCH];     // {A,B,X,Y} per channel

    const int b = blockIdx.x;
    const int tid = threadIdx.x;

    if (tid < FCH)
        par_s[tid] = ((const float4*)g_par)[(size_t)b * FCH + tid];

    // Zero only the 76 border cells of each plane
    for (int i = tid; i < FCH * 76; i += 324) {
        const int f = i / 76;
        const int k = i - f * 76;
        int idx;
        if (k < 20)      idx = k;                  // row 0
        else if (k < 40) idx = 380 + (k - 20);     // row 19
        else if (k < 58) idx = (k - 39) * PW;      // col 0, rows 1..18
        else             idx = (k - 57) * PW + 19; // col 19, rows 1..18
        bl[f][idx] = 0.f;
    }

    const float* base = fm + (size_t)b * VOL;
    const int py = tid / WW;
    const int px = tid - py * WW;

    // Pre-blend z into padded interior (trilinear == bilinear on blend)
    {
        const int pidx = (py + 1) * PW + (px + 1);
        #pragma unroll
        for (int f = 0; f < FCH; f++) {
            const float iz = f * (20.f / 19.f) - 0.5f;
            const float z0f = floorf(iz);
            const float wz = iz - z0f;
            const int z0 = (int)z0f;
            const float v0 = (z0 >= 0)      ? base[z0 * HWSZ + tid]       : 0.f;
            const float v1 = (z0 + 1 < FCH) ? base[(z0 + 1) * HWSZ + tid] : 0.f;
            bl[f][pidx] = (1.f - wz) * v0 + wz * v1;
        }
    }
    __syncthreads();

    {
        const float gx = px * (2.f / 17.f) - 1.f;
        const float gy = py * (2.f / 17.f) - 1.f;
        float* ob = out + (size_t)b * VOL + tid;

        #pragma unroll 4
        for (int f = 0; f < FCH; f++) {
            const float4 p = par_s[f];

            float ix = fmaf(p.x, gx, fmaf(-p.y, gy, p.z));  // A*gx - B*gy + X
            float iy = fmaf(p.y, gx, fmaf(p.x, gy, p.w));   // B*gx + A*gy + Y

            ix = fminf(fmaxf(ix, -1.f), 17.999998f);
            iy = fminf(fmaxf(iy, -1.f), 17.999998f);

            const float x0f = floorf(ix), y0f = floorf(iy);
            const float wx = ix - x0f, wy = iy - y0f;
            const int xi = (int)x0f + 1;   // [0,18]
            const int yi = (int)y0f + 1;   // [0,18]

            const float* q = &bl[f][yi * PW + xi];
            const float t00 = q[0],  t01 = q[1];
            const float t10 = q[PW], t11 = q[PW + 1];
            const float r0 = fmaf(wx, t01 - t00, t00);
            const float r1 = fmaf(wx, t11 - t10, t10);
            ob[f * HWSZ] = fmaf(wy, r1 - r0, r0);
        }
    }
}

// ---------------------------------------------------------------------------
extern "C" void kernel_launch(void* const* d_in, const int* in_sizes, int n_in,
                              void* d_out, int out_size)
{
    const float* feature_map = (const float*)d_in[0];
    const float* para_code   = (const float*)d_in[1];
    const float* W1 = (const float*)d_in[2];
    const float* b1 = (const float*)d_in[3];
    const float* Ws = (const float*)d_in[4];
    const float* bs = (const float*)d_in[5];
    const float* Wr = (const float*)d_in[6];
    const float* br = (const float*)d_in[7];
    const float* Wt = (const float*)d_in[8];
    const float* bt = (const float*)d_in[9];
    float* out = (float*)d_out;

    params_kernel<<<BATCH / TB, 256>>>(para_code, W1, b1, Ws, bs, Wr, br, Wt, bt);
    sample_kernel<<<BATCH, 324>>>(feature_map, out);
}

// round 16
// speedup vs baseline: 1.3645x; 1.0029x over previous
#include <cuda_runtime.h>
#include <cuda_bf16.h>
#include <math.h>

#define BATCH 4096
#define P 256
#define FCH 20
#define HH 18
#define WW 18
#define HWSZ (HH*WW)          // 324
#define VOL (FCH*HWSZ)        // 6480
#define TB 16                 // batches per CTA in params kernel
#define PI_CONST 3.14159f
#define PW 20                 // padded plane width (x in [-1,18] -> idx 0..19)
#define PAREA (PW*PW)         // 400

// Scratch: per (b,f): {A, B, X, Y} fully-fused affine (float4-aligned)
__device__ __align__(16) float g_par[(size_t)BATCH * FCH * 4];

// ---- packed fp32x2 helpers (Blackwell FFMA2, PTX-only) ---------------------
__device__ __forceinline__ void ffma2(unsigned long long& d,
                                      unsigned long long a,
                                      unsigned long long b) {
    asm("fma.rn.f32x2 %0, %1, %2, %0;" : "+l"(d) : "l"(a), "l"(b));
}
__device__ __forceinline__ unsigned long long splat2(float w) {
    unsigned long long r;
    asm("mov.b64 %0, {%1, %1};" : "=l"(r) : "f"(w));
    return r;
}
__device__ __forceinline__ float2 unpack2(unsigned long long v) {
    float2 r;
    asm("mov.b64 {%0, %1}, %2;" : "=f"(r.x), "=f"(r.y) : "l"(v));
    return r;
}

// ---- fast transcendentals (MUFU-based, ~1e-6 accuracy) ---------------------
__device__ __forceinline__ float fast_tanh(float x) {
    return 1.f - __fdividef(2.f, __expf(2.f * x) + 1.f);
}
__device__ __forceinline__ float fast_sigmoid(float x) {
    return __fdividef(1.f, 1.f + __expf(-x));
}

// ---------------------------------------------------------------------------
// Kernel 1 (R11/R13 version, measured 33.7us): MLP head -> fused params
// grid: BATCH/TB = 256 blocks, 256 threads
// ---------------------------------------------------------------------------
__global__ __launch_bounds__(256) void params_kernel(
    const float* __restrict__ pc,   // (B,P)
    const float* __restrict__ W1,   // (P,P)
    const float* __restrict__ b1,   // (P,)
    const float* __restrict__ Ws,   // (P,20)
    const float* __restrict__ bs,   // (20,)
    const float* __restrict__ Wr,   // (P,20)
    const float* __restrict__ br,   // (20,)
    const float* __restrict__ Wt,   // (P,40)
    const float* __restrict__ bt)   // (40,)
{
    __shared__ __align__(16) float pc_s[P][TB];   // transposed: [i][b]
    __shared__ __align__(16) float h_t[P][TB];    // h transposed: [i][b]
    __shared__ float red[3][80][TB];              // head partials

    const int tid = threadIdx.x;
    const int b0 = blockIdx.x * TB;

    #pragma unroll
    for (int b = 0; b < TB; b++)
        pc_s[tid][b] = pc[(size_t)(b0 + b) * P + tid];
    __syncthreads();

    unsigned long long accp[TB / 2];
    #pragma unroll
    for (int k = 0; k < TB / 2; k++) accp[k] = 0ull;

    const int U = 8;
    float cur[U], nxt[U];
    #pragma unroll
    for (int j = 0; j < U; j++) cur[j] = W1[j * P + tid];

    for (int i0 = 0; i0 < P; i0 += U) {
        const int inext = i0 + U;
        if (inext < P) {
            #pragma unroll
            for (int j = 0; j < U; j++) nxt[j] = W1[(inext + j) * P + tid];
        }
        #pragma unroll
        for (int j = 0; j < U; j++) {
            const unsigned long long wpj = splat2(cur[j]);
            const ulonglong2* pr = (const ulonglong2*)pc_s[i0 + j];
            const ulonglong2 q0 = pr[0], q1 = pr[1], q2 = pr[2], q3 = pr[3];
            ffma2(accp[0], q0.x, wpj);  ffma2(accp[1], q0.y, wpj);
            ffma2(accp[2], q1.x, wpj);  ffma2(accp[3], q1.y, wpj);
            ffma2(accp[4], q2.x, wpj);  ffma2(accp[5], q2.y, wpj);
            ffma2(accp[6], q3.x, wpj);  ffma2(accp[7], q3.y, wpj);
        }
        #pragma unroll
        for (int j = 0; j < U; j++) cur[j] = nxt[j];
    }

    const float bias1 = b1[tid];
    #pragma unroll
    for (int k = 0; k < TB / 2; k++) {
        const float2 f = unpack2(accp[k]);
        h_t[tid][2 * k + 0] = fmaxf(f.x + bias1, 0.f);
        h_t[tid][2 * k + 1] = fmaxf(f.y + bias1, 0.f);
    }
    __syncthreads();

    if (tid < 240) {
        const int col = tid % 80;
        const int seg = tid / 80;

        const float* wp;
        int ld;
        if (col < 20)      { wp = Ws + col;        ld = 20; }
        else if (col < 40) { wp = Wr + (col - 20); ld = 20; }
        else               { wp = Wt + (col - 40); ld = 40; }

        unsigned long long hacc[TB / 2];
        #pragma unroll
        for (int k = 0; k < TB / 2; k++) hacc[k] = 0ull;

        const float* wptr = wp + seg * ld;
        const int step = 3 * ld;
        for (int i = seg; i < P; i += 3) {
            const unsigned long long wpj = splat2(*wptr);
            wptr += step;
            const ulonglong2* hr = (const ulonglong2*)h_t[i];
            const ulonglong2 q0 = hr[0], q1 = hr[1], q2 = hr[2], q3 = hr[3];
            ffma2(hacc[0], q0.x, wpj);  ffma2(hacc[1], q0.y, wpj);
            ffma2(hacc[2], q1.x, wpj);  ffma2(hacc[3], q1.y, wpj);
            ffma2(hacc[4], q2.x, wpj);  ffma2(hacc[5], q2.y, wpj);
            ffma2(hacc[6], q3.x, wpj);  ffma2(hacc[7], q3.y, wpj);
        }
        #pragma unroll
        for (int k = 0; k < TB / 2; k++) {
            const float2 f = unpack2(hacc[k]);
            red[seg][col][2 * k + 0] = f.x;
            red[seg][col][2 * k + 1] = f.y;
        }
    }
    __syncthreads();

    for (int o = tid; o < TB * FCH; o += 256) {
        const int b = o / FCH;
        const int f = o - b * FCH;

        const float vs = red[0][f][b] + red[1][f][b] + red[2][f][b] + bs[f];
        const float vr = red[0][20 + f][b] + red[1][20 + f][b] + red[2][20 + f][b] + br[f];
        const float vt0 = red[0][40 + 2*f][b] + red[1][40 + 2*f][b] + red[2][40 + 2*f][b] + bt[2*f];
        const float vt1 = red[0][41 + 2*f][b] + red[1][41 + 2*f][b] + red[2][41 + 2*f][b] + bt[2*f + 1];

        const float scale = 2.f * fast_sigmoid(vs);
        const float ang = fast_tanh(vr) * PI_CONST;
        const float s = __sinf(ang);
        const float c = __cosf(ang);
        const float s9 = scale * 9.f;

        float4 out4;
        out4.x = c * s9;                               // A
        out4.y = s * s9;                               // B
        out4.z = (fast_tanh(vt0) + 1.f) * 9.f - 0.5f;  // X
        out4.w = (fast_tanh(vt1) + 1.f) * 9.f - 0.5f;  // Y
        ((float4*)g_par)[(size_t)(b0 + b) * FCH + f] = out4;
    }
}

// ---------------------------------------------------------------------------
// Kernel 2: register-cached z-blend (each input plane loaded ONCE, 20 LDG
// instead of 40; blend weights are compile-time constants after unroll),
// then per-channel affine bilinear sample. grid: BATCH blocks, 324 threads.
// ---------------------------------------------------------------------------
__global__ __launch_bounds__(324, 6) void sample_kernel(
    const float* __restrict__ fm,   // (B,20,18,18)
    float* __restrict__ out)        // (B,20,18,18)
{
    __shared__ __align__(16) float bl[FCH][PAREA];  // 32 KB padded planes
    __shared__ __align__(16) float4 par_s[FCH];     // {A,B,X,Y} per channel

    const int b = blockIdx.x;
    const int tid = threadIdx.x;

    if (tid < FCH)
        par_s[tid] = ((const float4*)g_par)[(size_t)b * FCH + tid];

    // Zero only the 76 border cells of each plane
    for (int i = tid; i < FCH * 76; i += 324) {
        const int f = i / 76;
        const int k = i - f * 76;
        int idx;
        if (k < 20)      idx = k;                  // row 0
        else if (k < 40) idx = 380 + (k - 20);     // row 19
        else if (k < 58) idx = (k - 39) * PW;      // col 0, rows 1..18
        else             idx = (k - 57) * PW + 19; // col 19, rows 1..18
        bl[f][idx] = 0.f;
    }

    const float* base = fm + (size_t)b * VOL;
    const int py = tid / WW;
    const int px = tid - py * WW;

    // Load each input plane once into registers (20 LDG, fully batched),
    // then blend in pure register FFMA (z0/wz constant-folded per f).
    {
        float v[FCH];
        #pragma unroll
        for (int z = 0; z < FCH; z++) v[z] = base[z * HWSZ + tid];

        const int pidx = (py + 1) * PW + (px + 1);
        #pragma unroll
        for (int f = 0; f < FCH; f++) {
            const float iz = f * (20.f / 19.f) - 0.5f;
            const float z0f = floorf(iz);
            const float wz = iz - z0f;
            const int z0 = (int)z0f;                   // compile-time after unroll
            const float v0 = (z0 >= 0)      ? v[(z0 >= 0) ? z0 : 0]            : 0.f;
            const float v1 = (z0 + 1 < FCH) ? v[(z0 + 1 < FCH) ? z0 + 1 : 0]   : 0.f;
            bl[f][pidx] = (1.f - wz) * v0 + wz * v1;
        }
    }
    __syncthreads();

    {
        const float gx = px * (2.f / 17.f) - 1.f;
        const float gy = py * (2.f / 17.f) - 1.f;
        float* ob = out + (size_t)b * VOL + tid;

        #pragma unroll 4
        for (int f = 0; f < FCH; f++) {
            const float4 p = par_s[f];

            float ix = fmaf(p.x, gx, fmaf(-p.y, gy, p.z));  // A*gx - B*gy + X
            float iy = fmaf(p.y, gx, fmaf(p.x, gy, p.w));   // B*gx + A*gy + Y

            ix = fminf(fmaxf(ix, -1.f), 17.999998f);
            iy = fminf(fmaxf(iy, -1.f), 17.999998f);

            const float x0f = floorf(ix), y0f = floorf(iy);
            const float wx = ix - x0f, wy = iy - y0f;
            const int xi = (int)x0f + 1;   // [0,18]
            const int yi = (int)y0f + 1;   // [0,18]

            const float* q = &bl[f][yi * PW + xi];
            const float t00 = q[0],  t01 = q[1];
            const float t10 = q[PW], t11 = q[PW + 1];
            const float r0 = fmaf(wx, t01 - t00, t00);
            const float r1 = fmaf(wx, t11 - t10, t10);
            ob[f * HWSZ] = fmaf(wy, r1 - r0, r0);
        }
    }
}

// ---------------------------------------------------------------------------
extern "C" void kernel_launch(void* const* d_in, const int* in_sizes, int n_in,
                              void* d_out, int out_size)
{
    const float* feature_map = (const float*)d_in[0];
    const float* para_code   = (const float*)d_in[1];
    const float* W1 = (const float*)d_in[2];
    const float* b1 = (const float*)d_in[3];
    const float* Ws = (const float*)d_in[4];
    const float* bs = (const float*)d_in[5];
    const float* Wr = (const float*)d_in[6];
    const float* br = (const float*)d_in[7];
    const float* Wt = (const float*)d_in[8];
    const float* bt = (const float*)d_in[9];
    float* out = (float*)d_out;

    params_kernel<<<BATCH / TB, 256>>>(para_code, W1, b1, Ws, bs, Wr, br, Wt, bt);
    sample_kernel<<<BATCH, 324>>>(feature_map, out);
}